// round 12
// baseline (speedup 1.0000x reference)
#include <cuda_runtime.h>
#include <cuda_bf16.h>

// Problem constants
#define NN   8192
#define KK   32
#define CC   16
#define RBFN 16
#define HH   64

// Dynamic shared-memory layout (in floats).
// Total dynamic = 12,272 floats = 49,088 B; static smem = 0.
// 49,088 <= 49,152 (48 KB default cap) -> legal without cudaFuncSetAttribute.
#define OFF_RBF  0        // 32*16  = 512
#define OFF_E    512      // 32*4   = 128
#define OFF_F0N  640      // 32*16  = 512
#define OFF_F1N  1152     // 32*48  = 1536
#define OFF_H1   2688     // 32*64  = 2048
#define OFF_H2   4736     // 32*64  = 2048
#define OFF_CTR  6784     // 32*48  = 1536
#define OFF_M    8320     // 65*48  = 3120   (nb_s aliases first 32 floats early)
#define OFF_RED  11440    // 16*48  = 768
#define OFF_ACC0 12208    // 16
#define OFF_ACC1 12224    // 48
#define SMEM_FLOATS 12272
#define SMEM_BYTES (SMEM_FLOATS * 4)

__device__ __forceinline__ float siluf(float x) {
    return __fdividef(x, 1.0f + __expf(-x));
}
__device__ __forceinline__ float sigmf(float x) {
    return __fdividef(1.0f, 1.0f + __expf(-x));
}

__global__ __launch_bounds__(256, 4)
void gtt_kernel(const float* __restrict__ f0, const float* __restrict__ f1,
                const float* __restrict__ rbf, const float* __restrict__ gt_edge,
                const float* __restrict__ W1, const float* __restrict__ b1,
                const float* __restrict__ W2, const float* __restrict__ b2,
                const float* __restrict__ W3, const float* __restrict__ b3,
                const float* __restrict__ ln_g0, const float* __restrict__ ln_b0,
                const float* __restrict__ ln_g1, const float* __restrict__ ln_b1,
                const float* __restrict__ gate_W0, const float* __restrict__ gate_b0,
                const float* __restrict__ gate_W1, const float* __restrict__ gate_b1,
                const float* __restrict__ res_W0, const float* __restrict__ res_W1,
                const int* __restrict__ nbr_idx,
                float* __restrict__ out)
{
    extern __shared__ float sm[];
    float* rbf_s = sm + OFF_RBF;
    float* e_s   = sm + OFF_E;
    float* f0n_s = sm + OFF_F0N;
    float* f1n_s = sm + OFF_F1N;
    float* h1_s  = sm + OFF_H1;
    float* h2_s  = sm + OFF_H2;
    float* ctr_s = sm + OFF_CTR;
    float* M_s   = sm + OFF_M;
    float* red_s = sm + OFF_RED;
    float* acc0  = sm + OFF_ACC0;
    float* acc1  = sm + OFF_ACC1;
    int*   nb_s  = (int*)(sm + OFF_M);   // aliases M_s; dead before M_s written

    const int tid = threadIdx.x;
    const int i   = blockIdx.x;

    // ---- Phase 1: node-local loads ----
    if (tid < KK) nb_s[tid] = nbr_idx[i * KK + tid];
    for (int idx = tid; idx < 512; idx += 256)
        rbf_s[idx] = rbf[i * 512 + idx];
    if (tid < 128) e_s[tid] = gt_edge[i * 128 + tid];
    if (tid < 64) { if (tid < 16) acc0[tid] = 0.f; else acc1[tid - 16] = 0.f; }
    __syncthreads();

    // ---- Phase 2: neighbor gathers ----
    for (int idx = tid; idx < 512; idx += 256) {
        int j = idx >> 4, c = idx & 15;
        f0n_s[idx] = f0[nb_s[j] * 16 + c];
    }
    for (int idx = tid; idx < 1536; idx += 256) {
        int j = idx / 48, r = idx - j * 48;
        f1n_s[idx] = f1[nb_s[j] * 48 + r];
    }
    __syncthreads();

    // ---- Interaction paths ----
    #pragma unroll
    for (int t = 0; t < 5; t++) {
        const int dd = (t == 0 || t == 3) ? 1 : 3;   // output vector dim
        const int ot = (t == 0 || t == 3) ? 0 : 1;   // which output accumulator
        const int md = 16 * dd;
        const float* W1t = W1 + t * RBFN * HH;
        const float* b1t = b1 + t * HH;
        const float* W2t = W2 + t * HH * HH;
        const float* b2t = b2 + t * HH;
        const float* W3t = W3 + t * HH * 256;
        const float* b3t = b3 + t * 256;

        // ---- h1 = silu(rbf @ W1 + b1) : [32 x 64] ----
        // float4 on rbf rows (contiguous in r); W1 scalar coalesced LDG.
        {
            int h = tid & 63, j0 = tid >> 6;
            float s[8];
            float bb = b1t[h];
            #pragma unroll
            for (int k = 0; k < 8; k++) s[k] = bb;
            #pragma unroll
            for (int rb = 0; rb < 4; rb++) {
                float w0 = W1t[(4 * rb + 0) * 64 + h];
                float w1 = W1t[(4 * rb + 1) * 64 + h];
                float w2 = W1t[(4 * rb + 2) * 64 + h];
                float w3v = W1t[(4 * rb + 3) * 64 + h];
                #pragma unroll
                for (int k = 0; k < 8; k++) {
                    float4 a = *(const float4*)&rbf_s[(j0 + 4 * k) * 16 + 4 * rb];
                    s[k] = fmaf(a.x, w0, s[k]);
                    s[k] = fmaf(a.y, w1, s[k]);
                    s[k] = fmaf(a.z, w2, s[k]);
                    s[k] = fmaf(a.w, w3v, s[k]);
                }
            }
            #pragma unroll
            for (int k = 0; k < 8; k++)
                h1_s[(j0 + 4 * k) * 64 + h] = siluf(s[k]);
        }
        __syncthreads();

        // ---- h2 = silu(h1 @ W2 + b2) : [32 x 64] ----
        // float4 on h1 rows (4 consecutive r); W2 scalar coalesced LDG (L2-hot).
        {
            int h = tid & 63, j0 = tid >> 6;
            float s[8];
            float bb = b2t[h];
            #pragma unroll
            for (int k = 0; k < 8; k++) s[k] = bb;
            #pragma unroll
            for (int hb = 0; hb < 16; hb++) {
                float w0 = W2t[(4 * hb + 0) * 64 + h];
                float w1 = W2t[(4 * hb + 1) * 64 + h];
                float w2 = W2t[(4 * hb + 2) * 64 + h];
                float w3v = W2t[(4 * hb + 3) * 64 + h];
                #pragma unroll
                for (int k = 0; k < 8; k++) {
                    float4 a = *(const float4*)&h1_s[(j0 + 4 * k) * 64 + 4 * hb];
                    s[k] = fmaf(a.x, w0, s[k]);
                    s[k] = fmaf(a.y, w1, s[k]);
                    s[k] = fmaf(a.z, w2, s[k]);
                    s[k] = fmaf(a.w, w3v, s[k]);
                }
            }
            #pragma unroll
            for (int k = 0; k < 8; k++)
                h2_s[(j0 + 4 * k) * 64 + h] = siluf(s[k]);
        }
        __syncthreads();

        // ---- contracted tensor ctr[j][c*dd+d] (path-specific, cheap) ----
        for (int idx = tid; idx < 32 * md; idx += 256) {
            int j = idx / md, cd = idx - j * md;
            float v;
            if (t == 0) {
                int c = cd;
                v = e_s[j * 4] * f0n_s[j * 16 + c];
            } else if (t == 1) {
                int c = cd / 3, d = cd - c * 3;
                v = e_s[j * 4 + 1 + d] * f0n_s[j * 16 + c];
            } else if (t == 2) {
                int c = cd / 3, d = cd - c * 3;
                v = e_s[j * 4] * f1n_s[j * 48 + c * 3 + d];
            } else if (t == 3) {
                int c = cd;
                v = e_s[j * 4 + 1] * f1n_s[j * 48 + c * 3]
                  + e_s[j * 4 + 2] * f1n_s[j * 48 + c * 3 + 1]
                  + e_s[j * 4 + 3] * f1n_s[j * 48 + c * 3 + 2];
            } else {
                int c = cd / 3, d = cd - c * 3;
                int d1 = (d + 1) % 3, d2 = (d + 2) % 3;
                v = f1n_s[j * 48 + c * 3 + d1] * e_s[j * 4 + 1 + d2]
                  - f1n_s[j * 48 + c * 3 + d2] * e_s[j * 4 + 1 + d1];
            }
            ctr_s[j * 48 + cd] = v;
        }
        __syncthreads();

        // ---- M[h][cd] = sum_j h2[j][h] * ctr[j][cd]  (h=64 row = bias row) ----
        {
            int h = tid >> 2, cq = tid & 3;
            int nc = md >> 2;          // 4 (dd=1) or 12 (dd=3)
            int cd0 = cq * nc;
            float s[12];
            #pragma unroll
            for (int m = 0; m < 12; m++) s[m] = 0.f;
            for (int j = 0; j < 32; j++) {
                float hv = h2_s[j * 64 + h];
                const float* cr = ctr_s + j * 48 + cd0;
                if (md == 48) {
                    #pragma unroll
                    for (int m = 0; m < 12; m += 4) {
                        float4 c4 = *(const float4*)&cr[m];
                        s[m + 0] = fmaf(hv, c4.x, s[m + 0]);
                        s[m + 1] = fmaf(hv, c4.y, s[m + 1]);
                        s[m + 2] = fmaf(hv, c4.z, s[m + 2]);
                        s[m + 3] = fmaf(hv, c4.w, s[m + 3]);
                    }
                } else {
                    float4 c4 = *(const float4*)&cr[0];
                    s[0] = fmaf(hv, c4.x, s[0]);
                    s[1] = fmaf(hv, c4.y, s[1]);
                    s[2] = fmaf(hv, c4.z, s[2]);
                    s[3] = fmaf(hv, c4.w, s[3]);
                }
            }
            if (md == 48) {
                #pragma unroll
                for (int m = 0; m < 12; m++) M_s[h * 48 + cd0 + m] = s[m];
            } else {
                #pragma unroll
                for (int m = 0; m < 4; m++) M_s[h * 48 + cd0 + m] = s[m];
            }
        }
        if (tid < md) {  // virtual bias row: sum_j ctr
            float s = 0.f;
            #pragma unroll 8
            for (int j = 0; j < 32; j++) s += ctr_s[j * 48 + tid];
            M_s[64 * 48 + tid] = s;
        }
        __syncthreads();

        // ---- msg[o][d] = sum_{h,c} M[h][c*dd+d] * W3[t,h,c*16+o] ----
        // W3 weights hoisted to registers per h-row; M rows read as float4 with
        // compile-time (c,d) decomposition of each component.
        {
            int o = tid & 15, grp = tid >> 4;
            float p0 = 0.f, p1 = 0.f, p2 = 0.f;

            #define GTT_ACC(vv, idx) do {                       \
                const int c_ = (idx) / 3, d_ = (idx) % 3;       \
                if (d_ == 0)      p0 = fmaf((vv), w[c_], p0);   \
                else if (d_ == 1) p1 = fmaf((vv), w[c_], p1);   \
                else              p2 = fmaf((vv), w[c_], p2);   \
            } while (0)

            #pragma unroll
            for (int hh = 0; hh < 4; hh++) {
                int h = grp * 4 + hh;
                const float* w3row = W3t + h * 256 + o;
                float w[16];
                #pragma unroll
                for (int c = 0; c < 16; c++) w[c] = w3row[c * 16];
                const float4* m4 = (const float4*)(M_s + h * 48);
                if (dd == 1) {
                    #pragma unroll
                    for (int q = 0; q < 4; q++) {
                        float4 m = m4[q];
                        p0 = fmaf(m.x, w[4 * q + 0], p0);
                        p0 = fmaf(m.y, w[4 * q + 1], p0);
                        p0 = fmaf(m.z, w[4 * q + 2], p0);
                        p0 = fmaf(m.w, w[4 * q + 3], p0);
                    }
                } else {
                    #pragma unroll
                    for (int q = 0; q < 12; q++) {
                        float4 m = m4[q];
                        GTT_ACC(m.x, 4 * q + 0);
                        GTT_ACC(m.y, 4 * q + 1);
                        GTT_ACC(m.z, 4 * q + 2);
                        GTT_ACC(m.w, 4 * q + 3);
                    }
                }
            }
            if (grp == 0) {  // bias row (h=64), weight = b3
                float w[16];
                #pragma unroll
                for (int c = 0; c < 16; c++) w[c] = b3t[c * 16 + o];
                const float4* m4 = (const float4*)(M_s + 64 * 48);
                if (dd == 1) {
                    #pragma unroll
                    for (int q = 0; q < 4; q++) {
                        float4 m = m4[q];
                        p0 = fmaf(m.x, w[4 * q + 0], p0);
                        p0 = fmaf(m.y, w[4 * q + 1], p0);
                        p0 = fmaf(m.z, w[4 * q + 2], p0);
                        p0 = fmaf(m.w, w[4 * q + 3], p0);
                    }
                } else {
                    #pragma unroll
                    for (int q = 0; q < 12; q++) {
                        float4 m = m4[q];
                        GTT_ACC(m.x, 4 * q + 0);
                        GTT_ACC(m.y, 4 * q + 1);
                        GTT_ACC(m.z, 4 * q + 2);
                        GTT_ACC(m.w, 4 * q + 3);
                    }
                }
            }
            #undef GTT_ACC

            red_s[grp * 48 + o * dd + 0] = p0;
            if (dd == 3) {
                red_s[grp * 48 + o * dd + 1] = p1;
                red_s[grp * 48 + o * dd + 2] = p2;
            }
        }
        __syncthreads();
        if (tid < md) {
            float s = 0.f;
            #pragma unroll
            for (int g = 0; g < 16; g++) s += red_s[g * 48 + tid];
            if (ot == 0) acc0[tid] += s;
            else         acc1[tid] += s;
        }
        __syncthreads();
    }

    // ---- Post: type_norm, gates, residual ----
    float* nrm = red_s;        // 32
    float* f0g = red_s + 32;   // 16
    float* o1n = red_s + 48;   // 48
    float* g1s = red_s + 96;   // 16

    if (tid < 16) {
        nrm[tid] = fmaxf(fabsf(acc0[tid]), 1e-8f);
        float a = acc1[tid * 3], b = acc1[tid * 3 + 1], c = acc1[tid * 3 + 2];
        nrm[16 + tid] = fmaxf(sqrtf(a * a + b * b + c * c), 1e-8f);
    }
    __syncthreads();
    if (tid < 16) {
        float mu0 = 0.f, mu1 = 0.f;
        #pragma unroll
        for (int c = 0; c < 16; c++) { mu0 += nrm[c]; mu1 += nrm[16 + c]; }
        mu0 *= 0.0625f; mu1 *= 0.0625f;
        float v0 = 0.f, v1 = 0.f;
        #pragma unroll
        for (int c = 0; c < 16; c++) {
            float d0 = nrm[c] - mu0;      v0 += d0 * d0;
            float d1 = nrm[16 + c] - mu1; v1 += d1 * d1;
        }
        v0 *= 0.0625f; v1 *= 0.0625f;
        float sc0 = (nrm[tid] - mu0) * rsqrtf(v0 + 1e-5f) * ln_g0[tid] + ln_b0[tid];
        float sc1 = (nrm[16 + tid] - mu1) * rsqrtf(v1 + 1e-5f) * ln_g1[tid] + ln_b1[tid];
        f0g[tid] = acc0[tid] / nrm[tid] * sc0;
        float inv1 = sc1 / nrm[16 + tid];
        o1n[tid * 3 + 0] = acc1[tid * 3 + 0] * inv1;
        o1n[tid * 3 + 1] = acc1[tid * 3 + 1] * inv1;
        o1n[tid * 3 + 2] = acc1[tid * 3 + 2] * inv1;
    }
    __syncthreads();
    if (tid < 16) {
        float z0 = gate_b0[tid], z1 = gate_b1[tid];
        #pragma unroll
        for (int c = 0; c < 16; c++) {
            z0 = fmaf(f0g[c], gate_W0[c * 16 + tid], z0);
            z1 = fmaf(f0g[c], gate_W1[c * 16 + tid], z1);
        }
        float g0 = sigmf(z0);
        g1s[tid] = sigmf(z1);
        float r = 0.f;
        #pragma unroll
        for (int c = 0; c < 16; c++)
            r = fmaf(f0[i * 16 + c], res_W0[c * 16 + tid], r);
        out[i * 16 + tid] = f0g[tid] * g0 + r;
    }
    __syncthreads();
    if (tid < 48) {
        int o = tid / 3, d = tid - o * 3;
        float r = 0.f;
        #pragma unroll
        for (int c = 0; c < 16; c++)
            r = fmaf(f1[(i * 16 + c) * 3 + d], res_W1[c * 16 + o], r);
        out[NN * 16 + i * 48 + tid] = o1n[tid] * g1s[o] + r;
    }
}

extern "C" void kernel_launch(void* const* d_in, const int* in_sizes, int n_in,
                              void* d_out, int out_size)
{
    (void)in_sizes; (void)n_in; (void)out_size;
    const float* f0       = (const float*)d_in[0];
    const float* f1       = (const float*)d_in[1];
    const float* rbf      = (const float*)d_in[2];
    const float* gt_edge  = (const float*)d_in[3];
    const float* W1       = (const float*)d_in[4];
    const float* b1       = (const float*)d_in[5];
    const float* W2       = (const float*)d_in[6];
    const float* b2       = (const float*)d_in[7];
    const float* W3       = (const float*)d_in[8];
    const float* b3       = (const float*)d_in[9];
    const float* ln_g0    = (const float*)d_in[10];
    const float* ln_b0    = (const float*)d_in[11];
    const float* ln_g1    = (const float*)d_in[12];
    const float* ln_b1    = (const float*)d_in[13];
    const float* gate_W0  = (const float*)d_in[14];
    const float* gate_b0  = (const float*)d_in[15];
    const float* gate_W1  = (const float*)d_in[16];
    const float* gate_b1  = (const float*)d_in[17];
    const float* res_W0   = (const float*)d_in[18];
    const float* res_W1   = (const float*)d_in[19];
    const int* nbr        = (const int*)d_in[20];
    float* out = (float*)d_out;

    gtt_kernel<<<NN, 256, SMEM_BYTES>>>(f0, f1, rbf, gt_edge, W1, b1, W2, b2, W3, b3,
                                        ln_g0, ln_b0, ln_g1, ln_b1,
                                        gate_W0, gate_b0, gate_W1, gate_b1,
                                        res_W0, res_W1, nbr, out);
}

// round 14
// speedup vs baseline: 1.1105x; 1.1105x over previous
#include <cuda_runtime.h>

#define NN   8192
#define KK   32
#define NROW (NN * KK)     // 262144 edge rows
#define HH   64

typedef unsigned long long ull;

// 5 * 262144 * 64 floats = 320 MB scratch for h2 activations (sanctioned
// __device__ global scratch; fully overwritten before read each call).
__device__ float g_h2[5L * NROW * HH];

__device__ __forceinline__ float siluf(float x) {
    return __fdividef(x, 1.0f + __expf(-x));
}
__device__ __forceinline__ float sigmf(float x) {
    return __fdividef(1.0f, 1.0f + __expf(-x));
}

// ---- packed f32x2 (FFMA2) helpers ----
__device__ __forceinline__ ull pk2(float x, float y) {
    ull r; asm("mov.b64 %0,{%1,%2};" : "=l"(r) : "f"(x), "f"(y)); return r;
}
__device__ __forceinline__ void upk2(float& x, float& y, ull v) {
    asm("mov.b64 {%0,%1},%2;" : "=f"(x), "=f"(y) : "l"(v));
}
__device__ __forceinline__ ull fma2(ull a, ull b, ull c) {
    ull d; asm("fma.rn.f32x2 %0,%1,%2,%3;" : "=l"(d) : "l"(a), "l"(b), "l"(c));
    return d;
}

// =========================================================================
// Kernel 1: radial MLP (rbf -> silu -> silu -> h2) as a batched GEMM.
// grid (NROW/128, 5); block 256. Tile: 128 rows x 64 h. Thread: 8r x 4h.
// acc[k][p] = (s[k][h0+2p], s[k][h0+2p+1]) packed; weights load as natural
// (w_even, w_odd) u64 pairs; activations duplicated via 1 pk2 per row.
// =========================================================================
__global__ __launch_bounds__(256)
void mlp_kernel(const float* __restrict__ rbf,
                const float* __restrict__ W1, const float* __restrict__ b1,
                const float* __restrict__ W2, const float* __restrict__ b2)
{
    __shared__ float rbfT[16 * 132];   // [k][row], padded
    __shared__ float h1T[64 * 132];    // [k][row], padded

    const int t    = blockIdx.y;
    const int base = blockIdx.x * 128;
    const int tid  = threadIdx.x;
    const float* W1t = W1 + t * 1024;
    const float* W2t = W2 + t * 4096;

    // fill rbfT transposed: rbf[(base+row)*16 + c] -> rbfT[c*132 + row]
    #pragma unroll
    for (int it = 0; it < 2; it++) {
        int idx = it * 256 + tid;            // 0..511
        int row = idx >> 2, cb = (idx & 3) * 4;
        float4 v = *(const float4*)&rbf[(base + row) * 16 + cb];
        rbfT[(cb + 0) * 132 + row] = v.x;
        rbfT[(cb + 1) * 132 + row] = v.y;
        rbfT[(cb + 2) * 132 + row] = v.z;
        rbfT[(cb + 3) * 132 + row] = v.w;
    }
    __syncthreads();

    const int hg = tid & 15, rg = tid >> 4;
    const int h0 = hg * 4,  r0 = rg * 8;

    ull acc[8][2];

    // ---- h1 = silu(rbf @ W1 + b1) ----
    {
        ulonglong2 bp = *(const ulonglong2*)&b1[t * 64 + h0];
        #pragma unroll
        for (int k = 0; k < 8; k++) { acc[k][0] = bp.x; acc[k][1] = bp.y; }
        #pragma unroll
        for (int r = 0; r < 16; r++) {
            ulonglong2 wv = *(const ulonglong2*)&W1t[r * 64 + h0];
            float4 a0 = *(const float4*)&rbfT[r * 132 + r0];
            float4 a1 = *(const float4*)&rbfT[r * 132 + r0 + 4];
            ull ap[8];
            ap[0] = pk2(a0.x, a0.x); ap[1] = pk2(a0.y, a0.y);
            ap[2] = pk2(a0.z, a0.z); ap[3] = pk2(a0.w, a0.w);
            ap[4] = pk2(a1.x, a1.x); ap[5] = pk2(a1.y, a1.y);
            ap[6] = pk2(a1.z, a1.z); ap[7] = pk2(a1.w, a1.w);
            #pragma unroll
            for (int k = 0; k < 8; k++) {
                acc[k][0] = fma2(ap[k], wv.x, acc[k][0]);
                acc[k][1] = fma2(ap[k], wv.y, acc[k][1]);
            }
        }
        float sv[8][4];
        #pragma unroll
        for (int k = 0; k < 8; k++) {
            float x0, x1, x2, x3;
            upk2(x0, x1, acc[k][0]);
            upk2(x2, x3, acc[k][1]);
            sv[k][0] = siluf(x0); sv[k][1] = siluf(x1);
            sv[k][2] = siluf(x2); sv[k][3] = siluf(x3);
        }
        #pragma unroll
        for (int c = 0; c < 4; c++) {
            *(float4*)&h1T[(h0 + c) * 132 + r0] =
                make_float4(sv[0][c], sv[1][c], sv[2][c], sv[3][c]);
            *(float4*)&h1T[(h0 + c) * 132 + r0 + 4] =
                make_float4(sv[4][c], sv[5][c], sv[6][c], sv[7][c]);
        }
    }
    __syncthreads();

    // ---- h2 = silu(h1 @ W2 + b2) ----
    {
        ulonglong2 bp = *(const ulonglong2*)&b2[t * 64 + h0];
        #pragma unroll
        for (int k = 0; k < 8; k++) { acc[k][0] = bp.x; acc[k][1] = bp.y; }
        #pragma unroll 16
        for (int r = 0; r < 64; r++) {
            ulonglong2 wv = *(const ulonglong2*)&W2t[r * 64 + h0];
            float4 a0 = *(const float4*)&h1T[r * 132 + r0];
            float4 a1 = *(const float4*)&h1T[r * 132 + r0 + 4];
            ull ap[8];
            ap[0] = pk2(a0.x, a0.x); ap[1] = pk2(a0.y, a0.y);
            ap[2] = pk2(a0.z, a0.z); ap[3] = pk2(a0.w, a0.w);
            ap[4] = pk2(a1.x, a1.x); ap[5] = pk2(a1.y, a1.y);
            ap[6] = pk2(a1.z, a1.z); ap[7] = pk2(a1.w, a1.w);
            #pragma unroll
            for (int k = 0; k < 8; k++) {
                acc[k][0] = fma2(ap[k], wv.x, acc[k][0]);
                acc[k][1] = fma2(ap[k], wv.y, acc[k][1]);
            }
        }
        float* dst = g_h2 + (t * NROW + base) * 64;
        #pragma unroll
        for (int k = 0; k < 8; k++) {
            float x0, x1, x2, x3;
            upk2(x0, x1, acc[k][0]);
            upk2(x2, x3, acc[k][1]);
            *(float4*)&dst[(r0 + k) * 64 + h0] =
                make_float4(siluf(x0), siluf(x1), siluf(x2), siluf(x3));
        }
    }
}

// =========================================================================
// Kernel 2: per-node contraction + W3 + type_norm/gates/residual.
// R10-proven structure minus the MLP stages; h2 read from g_h2.
// =========================================================================
#define OFF_E    0        // 128
#define OFF_F0N  128      // 512
#define OFF_F1N  640      // 1536
#define OFF_CTR  2176     // 1536
#define OFF_M    3712     // 65*48 = 3120  (nb_s aliases first 32 floats early)
#define OFF_RED  6832     // 768
#define OFF_ACC0 7600     // 16
#define OFF_ACC1 7616     // 48
#define SM2_FLOATS 7664
#define SM2_BYTES (SM2_FLOATS * 4)

__global__ __launch_bounds__(256, 4)
void gtt2_kernel(const float* __restrict__ f0, const float* __restrict__ f1,
                 const float* __restrict__ gt_edge,
                 const float* __restrict__ W3, const float* __restrict__ b3,
                 const float* __restrict__ ln_g0, const float* __restrict__ ln_b0,
                 const float* __restrict__ ln_g1, const float* __restrict__ ln_b1,
                 const float* __restrict__ gate_W0, const float* __restrict__ gate_b0,
                 const float* __restrict__ gate_W1, const float* __restrict__ gate_b1,
                 const float* __restrict__ res_W0, const float* __restrict__ res_W1,
                 const int* __restrict__ nbr_idx,
                 float* __restrict__ out)
{
    extern __shared__ float sm[];
    float* e_s   = sm + OFF_E;
    float* f0n_s = sm + OFF_F0N;
    float* f1n_s = sm + OFF_F1N;
    float* ctr_s = sm + OFF_CTR;
    float* M_s   = sm + OFF_M;
    float* red_s = sm + OFF_RED;
    float* acc0  = sm + OFF_ACC0;
    float* acc1  = sm + OFF_ACC1;
    int*   nb_s  = (int*)(sm + OFF_M);   // dead before M_s is written

    const int tid = threadIdx.x;
    const int i   = blockIdx.x;

    if (tid < KK) nb_s[tid] = nbr_idx[i * KK + tid];
    if (tid < 128) e_s[tid] = gt_edge[i * 128 + tid];
    if (tid < 64) { if (tid < 16) acc0[tid] = 0.f; else acc1[tid - 16] = 0.f; }
    __syncthreads();

    for (int idx = tid; idx < 512; idx += 256) {
        int j = idx >> 4, c = idx & 15;
        f0n_s[idx] = f0[nb_s[j] * 16 + c];
    }
    for (int idx = tid; idx < 1536; idx += 256) {
        int j = idx / 48, r = idx - j * 48;
        f1n_s[idx] = f1[nb_s[j] * 48 + r];
    }
    __syncthreads();

    #pragma unroll
    for (int t = 0; t < 5; t++) {
        const int dd = (t == 0 || t == 3) ? 1 : 3;
        const int ot = (t == 0 || t == 3) ? 0 : 1;
        const int md = 16 * dd;
        const float* W3t = W3 + t * HH * 256;
        const float* b3t = b3 + t * 256;
        const float* h2p = g_h2 + (t * NROW + i * KK) * 64;

        // ---- ctr[j][c*dd+d] ----
        for (int idx = tid; idx < 32 * md; idx += 256) {
            int j = idx / md, cd = idx - j * md;
            float v;
            if (t == 0) {
                v = e_s[j * 4] * f0n_s[j * 16 + cd];
            } else if (t == 1) {
                int c = cd / 3, d = cd - c * 3;
                v = e_s[j * 4 + 1 + d] * f0n_s[j * 16 + c];
            } else if (t == 2) {
                int c = cd / 3, d = cd - c * 3;
                v = e_s[j * 4] * f1n_s[j * 48 + c * 3 + d];
            } else if (t == 3) {
                v = e_s[j * 4 + 1] * f1n_s[j * 48 + cd * 3]
                  + e_s[j * 4 + 2] * f1n_s[j * 48 + cd * 3 + 1]
                  + e_s[j * 4 + 3] * f1n_s[j * 48 + cd * 3 + 2];
            } else {
                int c = cd / 3, d = cd - c * 3;
                int d1 = (d + 1) % 3, d2 = (d + 2) % 3;
                v = f1n_s[j * 48 + c * 3 + d1] * e_s[j * 4 + 1 + d2]
                  - f1n_s[j * 48 + c * 3 + d2] * e_s[j * 4 + 1 + d1];
            }
            ctr_s[j * 48 + cd] = v;
        }
        __syncthreads();

        // ---- M[h][cd] = sum_j h2[j][h] * ctr[j][cd] ----
        {
            int h = tid >> 2, cq = tid & 3;
            int nc = md >> 2;
            int cd0 = cq * nc;
            float s[12];
            #pragma unroll
            for (int m = 0; m < 12; m++) s[m] = 0.f;
            #pragma unroll 4
            for (int j = 0; j < 32; j++) {
                float hv = h2p[j * 64 + h];
                const float* cr = ctr_s + j * 48 + cd0;
                if (md == 48) {
                    #pragma unroll
                    for (int m = 0; m < 12; m += 4) {
                        float4 c4 = *(const float4*)&cr[m];
                        s[m + 0] = fmaf(hv, c4.x, s[m + 0]);
                        s[m + 1] = fmaf(hv, c4.y, s[m + 1]);
                        s[m + 2] = fmaf(hv, c4.z, s[m + 2]);
                        s[m + 3] = fmaf(hv, c4.w, s[m + 3]);
                    }
                } else {
                    float4 c4 = *(const float4*)&cr[0];
                    s[0] = fmaf(hv, c4.x, s[0]);
                    s[1] = fmaf(hv, c4.y, s[1]);
                    s[2] = fmaf(hv, c4.z, s[2]);
                    s[3] = fmaf(hv, c4.w, s[3]);
                }
            }
            if (md == 48) {
                #pragma unroll
                for (int m = 0; m < 12; m++) M_s[h * 48 + cd0 + m] = s[m];
            } else {
                #pragma unroll
                for (int m = 0; m < 4; m++) M_s[h * 48 + cd0 + m] = s[m];
            }
        }
        if (tid < md) {   // bias row
            float s = 0.f;
            #pragma unroll 8
            for (int j = 0; j < 32; j++) s += ctr_s[j * 48 + tid];
            M_s[64 * 48 + tid] = s;
        }
        __syncthreads();

        // ---- msg = M x W3 (+ b3 on bias row) ----
        {
            int o = tid & 15, grp = tid >> 4;
            float p0 = 0.f, p1 = 0.f, p2 = 0.f;

            #define GTT_ACC(vv, idx) do {                       \
                const int c_ = (idx) / 3, d_ = (idx) % 3;       \
                if (d_ == 0)      p0 = fmaf((vv), w[c_], p0);   \
                else if (d_ == 1) p1 = fmaf((vv), w[c_], p1);   \
                else              p2 = fmaf((vv), w[c_], p2);   \
            } while (0)

            #pragma unroll
            for (int hh = 0; hh < 4; hh++) {
                int h = grp * 4 + hh;
                const float* w3row = W3t + h * 256 + o;
                float w[16];
                #pragma unroll
                for (int c = 0; c < 16; c++) w[c] = w3row[c * 16];
                const float4* m4 = (const float4*)(M_s + h * 48);
                if (dd == 1) {
                    #pragma unroll
                    for (int q = 0; q < 4; q++) {
                        float4 m = m4[q];
                        p0 = fmaf(m.x, w[4 * q + 0], p0);
                        p0 = fmaf(m.y, w[4 * q + 1], p0);
                        p0 = fmaf(m.z, w[4 * q + 2], p0);
                        p0 = fmaf(m.w, w[4 * q + 3], p0);
                    }
                } else {
                    #pragma unroll
                    for (int q = 0; q < 12; q++) {
                        float4 m = m4[q];
                        GTT_ACC(m.x, 4 * q + 0);
                        GTT_ACC(m.y, 4 * q + 1);
                        GTT_ACC(m.z, 4 * q + 2);
                        GTT_ACC(m.w, 4 * q + 3);
                    }
                }
            }
            if (grp == 0) {
                float w[16];
                #pragma unroll
                for (int c = 0; c < 16; c++) w[c] = b3t[c * 16 + o];
                const float4* m4 = (const float4*)(M_s + 64 * 48);
                if (dd == 1) {
                    #pragma unroll
                    for (int q = 0; q < 4; q++) {
                        float4 m = m4[q];
                        p0 = fmaf(m.x, w[4 * q + 0], p0);
                        p0 = fmaf(m.y, w[4 * q + 1], p0);
                        p0 = fmaf(m.z, w[4 * q + 2], p0);
                        p0 = fmaf(m.w, w[4 * q + 3], p0);
                    }
                } else {
                    #pragma unroll
                    for (int q = 0; q < 12; q++) {
                        float4 m = m4[q];
                        GTT_ACC(m.x, 4 * q + 0);
                        GTT_ACC(m.y, 4 * q + 1);
                        GTT_ACC(m.z, 4 * q + 2);
                        GTT_ACC(m.w, 4 * q + 3);
                    }
                }
            }
            #undef GTT_ACC

            red_s[grp * 48 + o * dd + 0] = p0;
            if (dd == 3) {
                red_s[grp * 48 + o * dd + 1] = p1;
                red_s[grp * 48 + o * dd + 2] = p2;
            }
        }
        __syncthreads();
        if (tid < md) {
            float s = 0.f;
            #pragma unroll
            for (int g = 0; g < 16; g++) s += red_s[g * 48 + tid];
            if (ot == 0) acc0[tid] += s;
            else         acc1[tid] += s;
        }
        __syncthreads();
    }

    // ---- type_norm, gates, residual ----
    float* nrm = red_s;
    float* f0g = red_s + 32;
    float* o1n = red_s + 48;
    float* g1s = red_s + 96;

    if (tid < 16) {
        nrm[tid] = fmaxf(fabsf(acc0[tid]), 1e-8f);
        float a = acc1[tid * 3], b = acc1[tid * 3 + 1], c = acc1[tid * 3 + 2];
        nrm[16 + tid] = fmaxf(sqrtf(a * a + b * b + c * c), 1e-8f);
    }
    __syncthreads();
    if (tid < 16) {
        float mu0 = 0.f, mu1 = 0.f;
        #pragma unroll
        for (int c = 0; c < 16; c++) { mu0 += nrm[c]; mu1 += nrm[16 + c]; }
        mu0 *= 0.0625f; mu1 *= 0.0625f;
        float v0 = 0.f, v1 = 0.f;
        #pragma unroll
        for (int c = 0; c < 16; c++) {
            float d0 = nrm[c] - mu0;      v0 += d0 * d0;
            float d1 = nrm[16 + c] - mu1; v1 += d1 * d1;
        }
        v0 *= 0.0625f; v1 *= 0.0625f;
        float sc0 = (nrm[tid] - mu0) * rsqrtf(v0 + 1e-5f) * ln_g0[tid] + ln_b0[tid];
        float sc1 = (nrm[16 + tid] - mu1) * rsqrtf(v1 + 1e-5f) * ln_g1[tid] + ln_b1[tid];
        f0g[tid] = acc0[tid] / nrm[tid] * sc0;
        float inv1 = sc1 / nrm[16 + tid];
        o1n[tid * 3 + 0] = acc1[tid * 3 + 0] * inv1;
        o1n[tid * 3 + 1] = acc1[tid * 3 + 1] * inv1;
        o1n[tid * 3 + 2] = acc1[tid * 3 + 2] * inv1;
    }
    __syncthreads();
    if (tid < 16) {
        float z0 = gate_b0[tid], z1 = gate_b1[tid];
        #pragma unroll
        for (int c = 0; c < 16; c++) {
            z0 = fmaf(f0g[c], gate_W0[c * 16 + tid], z0);
            z1 = fmaf(f0g[c], gate_W1[c * 16 + tid], z1);
        }
        float g0 = sigmf(z0);
        g1s[tid] = sigmf(z1);
        float r = 0.f;
        #pragma unroll
        for (int c = 0; c < 16; c++)
            r = fmaf(f0[i * 16 + c], res_W0[c * 16 + tid], r);
        out[i * 16 + tid] = f0g[tid] * g0 + r;
    }
    __syncthreads();
    if (tid < 48) {
        int o = tid / 3, d = tid - o * 3;
        float r = 0.f;
        #pragma unroll
        for (int c = 0; c < 16; c++)
            r = fmaf(f1[(i * 16 + c) * 3 + d], res_W1[c * 16 + o], r);
        out[NN * 16 + i * 48 + tid] = o1n[tid] * g1s[o] + r;
    }
}

extern "C" void kernel_launch(void* const* d_in, const int* in_sizes, int n_in,
                              void* d_out, int out_size)
{
    (void)in_sizes; (void)n_in; (void)out_size;
    const float* f0       = (const float*)d_in[0];
    const float* f1       = (const float*)d_in[1];
    const float* rbf      = (const float*)d_in[2];
    const float* gt_edge  = (const float*)d_in[3];
    const float* W1       = (const float*)d_in[4];
    const float* b1       = (const float*)d_in[5];
    const float* W2       = (const float*)d_in[6];
    const float* b2       = (const float*)d_in[7];
    const float* W3       = (const float*)d_in[8];
    const float* b3       = (const float*)d_in[9];
    const float* ln_g0    = (const float*)d_in[10];
    const float* ln_b0    = (const float*)d_in[11];
    const float* ln_g1    = (const float*)d_in[12];
    const float* ln_b1    = (const float*)d_in[13];
    const float* gate_W0  = (const float*)d_in[14];
    const float* gate_b0  = (const float*)d_in[15];
    const float* gate_W1  = (const float*)d_in[16];
    const float* gate_b1  = (const float*)d_in[17];
    const float* res_W0   = (const float*)d_in[18];
    const float* res_W1   = (const float*)d_in[19];
    const int* nbr        = (const int*)d_in[20];
    float* out = (float*)d_out;

    mlp_kernel<<<dim3(NROW / 128, 5, 1), 256>>>(rbf, W1, b1, W2, b2);
    gtt2_kernel<<<NN, 256, SM2_BYTES>>>(f0, f1, gt_edge, W3, b3,
                                        ln_g0, ln_b0, ln_g1, ln_b1,
                                        gate_W0, gate_b0, gate_W1, gate_b1,
                                        res_W0, res_W1, nbr, out);
}

// round 16
// speedup vs baseline: 1.1847x; 1.0668x over previous
#include <cuda_runtime.h>

#define NN   8192
#define KK   32
#define NROW (NN * KK)     // 262144 edge rows
#define HH   64

typedef unsigned long long ull;

// Scratch: h2 activations (320 MB) + transposed W3/b3. All fully rewritten
// before being read on every call (deterministic).
__device__ float g_h2[5L * NROW * HH];
__device__ float g_W3T[5 * 64 * 4 * 16 * 4];   // [t][h][c4][o][cc]
__device__ float g_b3T[5 * 4 * 16 * 4];        // [t][c4][o][cc]

__device__ __forceinline__ float siluf(float x) {
    return __fdividef(x, 1.0f + __expf(-x));
}
__device__ __forceinline__ float sigmf(float x) {
    return __fdividef(1.0f, 1.0f + __expf(-x));
}

// ---- packed f32x2 (FFMA2) helpers ----
__device__ __forceinline__ ull pk2(float x, float y) {
    ull r; asm("mov.b64 %0,{%1,%2};" : "=l"(r) : "f"(x), "f"(y)); return r;
}
__device__ __forceinline__ void upk2(float& x, float& y, ull v) {
    asm("mov.b64 {%0,%1},%2;" : "=f"(x), "=f"(y) : "l"(v));
}
__device__ __forceinline__ ull fma2(ull a, ull b, ull c) {
    ull d; asm("fma.rn.f32x2 %0,%1,%2,%3;" : "=l"(d) : "l"(a), "l"(b), "l"(c));
    return d;
}

// =========================================================================
// Kernel 0: transpose W3 -> W3T[t][h][c4][o][cc] and b3 -> b3T[t][c4][o][cc]
// so the gtt2 weight loads become contiguous LDG.128 across lanes.
// index: t*16384 + h*256 + c4*64 + o*4 + cc   (c = c4*4+cc)
// =========================================================================
__global__ __launch_bounds__(256)
void tw3_kernel(const float* __restrict__ W3, const float* __restrict__ b3)
{
    int g = blockIdx.x * 256 + threadIdx.x;
    if (g < 81920) {
        int cc = g & 3, o = (g >> 2) & 15, c4 = (g >> 6) & 3;
        int h = (g >> 8) & 63, t = g >> 14;
        g_W3T[g] = W3[t * 16384 + h * 256 + (c4 * 4 + cc) * 16 + o];
    }
    if (g < 1280) {
        int cc = g & 3, o = (g >> 2) & 15, c4 = (g >> 6) & 3, t = g >> 8;
        g_b3T[g] = b3[t * 256 + (c4 * 4 + cc) * 16 + o];
    }
}

// =========================================================================
// Kernel 1: radial MLP (rbf -> silu -> silu -> h2), batched GEMM (proven R14).
// =========================================================================
__global__ __launch_bounds__(256)
void mlp_kernel(const float* __restrict__ rbf,
                const float* __restrict__ W1, const float* __restrict__ b1,
                const float* __restrict__ W2, const float* __restrict__ b2)
{
    __shared__ float rbfT[16 * 132];
    __shared__ float h1T[64 * 132];

    const int t    = blockIdx.y;
    const int base = blockIdx.x * 128;
    const int tid  = threadIdx.x;
    const float* W1t = W1 + t * 1024;
    const float* W2t = W2 + t * 4096;

    #pragma unroll
    for (int it = 0; it < 2; it++) {
        int idx = it * 256 + tid;
        int row = idx >> 2, cb = (idx & 3) * 4;
        float4 v = *(const float4*)&rbf[(base + row) * 16 + cb];
        rbfT[(cb + 0) * 132 + row] = v.x;
        rbfT[(cb + 1) * 132 + row] = v.y;
        rbfT[(cb + 2) * 132 + row] = v.z;
        rbfT[(cb + 3) * 132 + row] = v.w;
    }
    __syncthreads();

    const int hg = tid & 15, rg = tid >> 4;
    const int h0 = hg * 4,  r0 = rg * 8;

    ull acc[8][2];

    {   // h1 = silu(rbf @ W1 + b1)
        ulonglong2 bp = *(const ulonglong2*)&b1[t * 64 + h0];
        #pragma unroll
        for (int k = 0; k < 8; k++) { acc[k][0] = bp.x; acc[k][1] = bp.y; }
        #pragma unroll
        for (int r = 0; r < 16; r++) {
            ulonglong2 wv = *(const ulonglong2*)&W1t[r * 64 + h0];
            float4 a0 = *(const float4*)&rbfT[r * 132 + r0];
            float4 a1 = *(const float4*)&rbfT[r * 132 + r0 + 4];
            ull ap[8];
            ap[0] = pk2(a0.x, a0.x); ap[1] = pk2(a0.y, a0.y);
            ap[2] = pk2(a0.z, a0.z); ap[3] = pk2(a0.w, a0.w);
            ap[4] = pk2(a1.x, a1.x); ap[5] = pk2(a1.y, a1.y);
            ap[6] = pk2(a1.z, a1.z); ap[7] = pk2(a1.w, a1.w);
            #pragma unroll
            for (int k = 0; k < 8; k++) {
                acc[k][0] = fma2(ap[k], wv.x, acc[k][0]);
                acc[k][1] = fma2(ap[k], wv.y, acc[k][1]);
            }
        }
        float sv[8][4];
        #pragma unroll
        for (int k = 0; k < 8; k++) {
            float x0, x1, x2, x3;
            upk2(x0, x1, acc[k][0]);
            upk2(x2, x3, acc[k][1]);
            sv[k][0] = siluf(x0); sv[k][1] = siluf(x1);
            sv[k][2] = siluf(x2); sv[k][3] = siluf(x3);
        }
        #pragma unroll
        for (int c = 0; c < 4; c++) {
            *(float4*)&h1T[(h0 + c) * 132 + r0] =
                make_float4(sv[0][c], sv[1][c], sv[2][c], sv[3][c]);
            *(float4*)&h1T[(h0 + c) * 132 + r0 + 4] =
                make_float4(sv[4][c], sv[5][c], sv[6][c], sv[7][c]);
        }
    }
    __syncthreads();

    {   // h2 = silu(h1 @ W2 + b2)
        ulonglong2 bp = *(const ulonglong2*)&b2[t * 64 + h0];
        #pragma unroll
        for (int k = 0; k < 8; k++) { acc[k][0] = bp.x; acc[k][1] = bp.y; }
        #pragma unroll 16
        for (int r = 0; r < 64; r++) {
            ulonglong2 wv = *(const ulonglong2*)&W2t[r * 64 + h0];
            float4 a0 = *(const float4*)&h1T[r * 132 + r0];
            float4 a1 = *(const float4*)&h1T[r * 132 + r0 + 4];
            ull ap[8];
            ap[0] = pk2(a0.x, a0.x); ap[1] = pk2(a0.y, a0.y);
            ap[2] = pk2(a0.z, a0.z); ap[3] = pk2(a0.w, a0.w);
            ap[4] = pk2(a1.x, a1.x); ap[5] = pk2(a1.y, a1.y);
            ap[6] = pk2(a1.z, a1.z); ap[7] = pk2(a1.w, a1.w);
            #pragma unroll
            for (int k = 0; k < 8; k++) {
                acc[k][0] = fma2(ap[k], wv.x, acc[k][0]);
                acc[k][1] = fma2(ap[k], wv.y, acc[k][1]);
            }
        }
        float* dst = g_h2 + (long)(t * NROW + base) * 64;
        #pragma unroll
        for (int k = 0; k < 8; k++) {
            float x0, x1, x2, x3;
            upk2(x0, x1, acc[k][0]);
            upk2(x2, x3, acc[k][1]);
            *(float4*)&dst[(r0 + k) * 64 + h0] =
                make_float4(siluf(x0), siluf(x1), siluf(x2), siluf(x3));
        }
    }
}

// =========================================================================
// Kernel 2: per-node contraction + W3 + type_norm/gates/residual.
// M-stage retiled (h-quad x col-quad, vector loads); W3-stage uses W3T.
// =========================================================================
#define OFF_E    0        // 128
#define OFF_F0N  128      // 512
#define OFF_F1N  640      // 1536
#define OFF_CTR  2176     // 1536
#define OFF_M    3712     // 65*48 = 3120  (nb_s aliases first 32 floats early)
#define OFF_RED  6832     // 768
#define OFF_ACC0 7600     // 16
#define OFF_ACC1 7616     // 48
#define SM2_FLOATS 7664
#define SM2_BYTES (SM2_FLOATS * 4)

__global__ __launch_bounds__(256, 4)
void gtt2_kernel(const float* __restrict__ f0, const float* __restrict__ f1,
                 const float* __restrict__ gt_edge,
                 const float* __restrict__ ln_g0, const float* __restrict__ ln_b0,
                 const float* __restrict__ ln_g1, const float* __restrict__ ln_b1,
                 const float* __restrict__ gate_W0, const float* __restrict__ gate_b0,
                 const float* __restrict__ gate_W1, const float* __restrict__ gate_b1,
                 const float* __restrict__ res_W0, const float* __restrict__ res_W1,
                 const int* __restrict__ nbr_idx,
                 float* __restrict__ out)
{
    extern __shared__ float sm[];
    float* e_s   = sm + OFF_E;
    float* f0n_s = sm + OFF_F0N;
    float* f1n_s = sm + OFF_F1N;
    float* ctr_s = sm + OFF_CTR;
    float* M_s   = sm + OFF_M;
    float* red_s = sm + OFF_RED;
    float* acc0  = sm + OFF_ACC0;
    float* acc1  = sm + OFF_ACC1;
    int*   nb_s  = (int*)(sm + OFF_M);

    const int tid = threadIdx.x;
    const int i   = blockIdx.x;

    if (tid < KK) nb_s[tid] = nbr_idx[i * KK + tid];
    if (tid < 128) e_s[tid] = gt_edge[i * 128 + tid];
    if (tid < 64) { if (tid < 16) acc0[tid] = 0.f; else acc1[tid - 16] = 0.f; }
    __syncthreads();

    for (int idx = tid; idx < 512; idx += 256) {
        int j = idx >> 4, c = idx & 15;
        f0n_s[idx] = f0[nb_s[j] * 16 + c];
    }
    for (int idx = tid; idx < 1536; idx += 256) {
        int j = idx / 48, r = idx - j * 48;
        f1n_s[idx] = f1[nb_s[j] * 48 + r];
    }
    __syncthreads();

    #pragma unroll
    for (int t = 0; t < 5; t++) {
        const int dd = (t == 0 || t == 3) ? 1 : 3;
        const int ot = (t == 0 || t == 3) ? 0 : 1;
        const int md = 16 * dd;
        const float* h2p = g_h2 + (long)(t * NROW + i * KK) * 64;

        // ---- ctr[j][c*dd+d] ----
        for (int idx = tid; idx < 32 * md; idx += 256) {
            int j = idx / md, cd = idx - j * md;
            float v;
            if (t == 0) {
                v = e_s[j * 4] * f0n_s[j * 16 + cd];
            } else if (t == 1) {
                int c = cd / 3, d = cd - c * 3;
                v = e_s[j * 4 + 1 + d] * f0n_s[j * 16 + c];
            } else if (t == 2) {
                int c = cd / 3, d = cd - c * 3;
                v = e_s[j * 4] * f1n_s[j * 48 + c * 3 + d];
            } else if (t == 3) {
                v = e_s[j * 4 + 1] * f1n_s[j * 48 + cd * 3]
                  + e_s[j * 4 + 2] * f1n_s[j * 48 + cd * 3 + 1]
                  + e_s[j * 4 + 3] * f1n_s[j * 48 + cd * 3 + 2];
            } else {
                int c = cd / 3, d = cd - c * 3;
                int d1 = (d + 1) % 3, d2 = (d + 2) % 3;
                v = f1n_s[j * 48 + c * 3 + d1] * e_s[j * 4 + 1 + d2]
                  - f1n_s[j * 48 + c * 3 + d2] * e_s[j * 4 + 1 + d1];
            }
            ctr_s[j * 48 + cd] = v;
        }
        __syncthreads();

        // ---- M[h][cd] = sum_j h2[j][h]*ctr[j][cd]: (h-quad x col-quad) ----
        {
            const int hq = tid & 15;      // h = hq*4 + a
            const int cg = tid >> 4;      // cols cg*4 .. cg*4+3
            const int nc = md >> 2;       // 4 (dd=1) or 12 (dd=3)
            if (cg < nc) {
                float a0x=0,a0y=0,a0z=0,a0w=0, a1x=0,a1y=0,a1z=0,a1w=0;
                float a2x=0,a2y=0,a2z=0,a2w=0, a3x=0,a3y=0,a3z=0,a3w=0;
                #pragma unroll 4
                for (int j = 0; j < 32; j++) {
                    float4 hv = *(const float4*)&h2p[j * 64 + hq * 4];
                    float4 cv = *(const float4*)&ctr_s[j * 48 + cg * 4];
                    a0x = fmaf(hv.x, cv.x, a0x); a0y = fmaf(hv.x, cv.y, a0y);
                    a0z = fmaf(hv.x, cv.z, a0z); a0w = fmaf(hv.x, cv.w, a0w);
                    a1x = fmaf(hv.y, cv.x, a1x); a1y = fmaf(hv.y, cv.y, a1y);
                    a1z = fmaf(hv.y, cv.z, a1z); a1w = fmaf(hv.y, cv.w, a1w);
                    a2x = fmaf(hv.z, cv.x, a2x); a2y = fmaf(hv.z, cv.y, a2y);
                    a2z = fmaf(hv.z, cv.z, a2z); a2w = fmaf(hv.z, cv.w, a2w);
                    a3x = fmaf(hv.w, cv.x, a3x); a3y = fmaf(hv.w, cv.y, a3y);
                    a3z = fmaf(hv.w, cv.z, a3z); a3w = fmaf(hv.w, cv.w, a3w);
                }
                *(float4*)&M_s[(hq * 4 + 0) * 48 + cg * 4] = make_float4(a0x,a0y,a0z,a0w);
                *(float4*)&M_s[(hq * 4 + 1) * 48 + cg * 4] = make_float4(a1x,a1y,a1z,a1w);
                *(float4*)&M_s[(hq * 4 + 2) * 48 + cg * 4] = make_float4(a2x,a2y,a2z,a2w);
                *(float4*)&M_s[(hq * 4 + 3) * 48 + cg * 4] = make_float4(a3x,a3y,a3z,a3w);
            }
        }
        if (tid < md) {   // bias row: sum_j ctr
            float s = 0.f;
            #pragma unroll 8
            for (int j = 0; j < 32; j++) s += ctr_s[j * 48 + tid];
            M_s[64 * 48 + tid] = s;
        }
        __syncthreads();

        // ---- msg = M x W3 (+ b3 on bias row); weights via W3T LDG.128 ----
        {
            int o = tid & 15, grp = tid >> 4;
            float p0 = 0.f, p1 = 0.f, p2 = 0.f;

            #define GTT_ACC(vv, idx) do {                         \
                const int c_ = (idx) / 3, d_ = (idx) % 3;         \
                const float w_ = (c_ & 3) == 0 ? wq[c_>>2].x :    \
                                 (c_ & 3) == 1 ? wq[c_>>2].y :    \
                                 (c_ & 3) == 2 ? wq[c_>>2].z : wq[c_>>2].w; \
                if (d_ == 0)      p0 = fmaf((vv), w_, p0);        \
                else if (d_ == 1) p1 = fmaf((vv), w_, p1);        \
                else              p2 = fmaf((vv), w_, p2);        \
            } while (0)

            #pragma unroll
            for (int hh = 0; hh < 4; hh++) {
                int h = grp * 4 + hh;
                float4 wq[4];
                #pragma unroll
                for (int c4 = 0; c4 < 4; c4++)
                    wq[c4] = *(const float4*)&g_W3T[((t * 64 + h) * 4 + c4) * 64 + o * 4];
                const float4* m4 = (const float4*)(M_s + h * 48);
                if (dd == 1) {
                    #pragma unroll
                    for (int q = 0; q < 4; q++) {
                        float4 m = m4[q];
                        p0 = fmaf(m.x, wq[q].x, p0);
                        p0 = fmaf(m.y, wq[q].y, p0);
                        p0 = fmaf(m.z, wq[q].z, p0);
                        p0 = fmaf(m.w, wq[q].w, p0);
                    }
                } else {
                    #pragma unroll
                    for (int q = 0; q < 12; q++) {
                        float4 m = m4[q];
                        GTT_ACC(m.x, 4 * q + 0);
                        GTT_ACC(m.y, 4 * q + 1);
                        GTT_ACC(m.z, 4 * q + 2);
                        GTT_ACC(m.w, 4 * q + 3);
                    }
                }
            }
            if (grp == 0) {   // bias row, weights = b3T
                float4 wq[4];
                #pragma unroll
                for (int c4 = 0; c4 < 4; c4++)
                    wq[c4] = *(const float4*)&g_b3T[(t * 4 + c4) * 64 + o * 4];
                const float4* m4 = (const float4*)(M_s + 64 * 48);
                if (dd == 1) {
                    #pragma unroll
                    for (int q = 0; q < 4; q++) {
                        float4 m = m4[q];
                        p0 = fmaf(m.x, wq[q].x, p0);
                        p0 = fmaf(m.y, wq[q].y, p0);
                        p0 = fmaf(m.z, wq[q].z, p0);
                        p0 = fmaf(m.w, wq[q].w, p0);
                    }
                } else {
                    #pragma unroll
                    for (int q = 0; q < 12; q++) {
                        float4 m = m4[q];
                        GTT_ACC(m.x, 4 * q + 0);
                        GTT_ACC(m.y, 4 * q + 1);
                        GTT_ACC(m.z, 4 * q + 2);
                        GTT_ACC(m.w, 4 * q + 3);
                    }
                }
            }
            #undef GTT_ACC

            red_s[grp * 48 + o * dd + 0] = p0;
            if (dd == 3) {
                red_s[grp * 48 + o * dd + 1] = p1;
                red_s[grp * 48 + o * dd + 2] = p2;
            }
        }
        __syncthreads();
        if (tid < md) {
            float s = 0.f;
            #pragma unroll
            for (int g = 0; g < 16; g++) s += red_s[g * 48 + tid];
            if (ot == 0) acc0[tid] += s;
            else         acc1[tid] += s;
        }
        __syncthreads();
    }

    // ---- type_norm, gates, residual ----
    float* nrm = red_s;
    float* f0g = red_s + 32;
    float* o1n = red_s + 48;
    float* g1s = red_s + 96;

    if (tid < 16) {
        nrm[tid] = fmaxf(fabsf(acc0[tid]), 1e-8f);
        float a = acc1[tid * 3], b = acc1[tid * 3 + 1], c = acc1[tid * 3 + 2];
        nrm[16 + tid] = fmaxf(sqrtf(a * a + b * b + c * c), 1e-8f);
    }
    __syncthreads();
    if (tid < 16) {
        float mu0 = 0.f, mu1 = 0.f;
        #pragma unroll
        for (int c = 0; c < 16; c++) { mu0 += nrm[c]; mu1 += nrm[16 + c]; }
        mu0 *= 0.0625f; mu1 *= 0.0625f;
        float v0 = 0.f, v1 = 0.f;
        #pragma unroll
        for (int c = 0; c < 16; c++) {
            float d0 = nrm[c] - mu0;      v0 += d0 * d0;
            float d1 = nrm[16 + c] - mu1; v1 += d1 * d1;
        }
        v0 *= 0.0625f; v1 *= 0.0625f;
        float sc0 = (nrm[tid] - mu0) * rsqrtf(v0 + 1e-5f) * ln_g0[tid] + ln_b0[tid];
        float sc1 = (nrm[16 + tid] - mu1) * rsqrtf(v1 + 1e-5f) * ln_g1[tid] + ln_b1[tid];
        f0g[tid] = acc0[tid] / nrm[tid] * sc0;
        float inv1 = sc1 / nrm[16 + tid];
        o1n[tid * 3 + 0] = acc1[tid * 3 + 0] * inv1;
        o1n[tid * 3 + 1] = acc1[tid * 3 + 1] * inv1;
        o1n[tid * 3 + 2] = acc1[tid * 3 + 2] * inv1;
    }
    __syncthreads();
    if (tid < 16) {
        float z0 = gate_b0[tid], z1 = gate_b1[tid];
        #pragma unroll
        for (int c = 0; c < 16; c++) {
            z0 = fmaf(f0g[c], gate_W0[c * 16 + tid], z0);
            z1 = fmaf(f0g[c], gate_W1[c * 16 + tid], z1);
        }
        float g0 = sigmf(z0);
        g1s[tid] = sigmf(z1);
        float r = 0.f;
        #pragma unroll
        for (int c = 0; c < 16; c++)
            r = fmaf(f0[i * 16 + c], res_W0[c * 16 + tid], r);
        out[i * 16 + tid] = f0g[tid] * g0 + r;
    }
    __syncthreads();
    if (tid < 48) {
        int o = tid / 3, d = tid - o * 3;
        float r = 0.f;
        #pragma unroll
        for (int c = 0; c < 16; c++)
            r = fmaf(f1[(i * 16 + c) * 3 + d], res_W1[c * 16 + o], r);
        out[NN * 16 + i * 48 + tid] = o1n[tid] * g1s[o] + r;
    }
}

extern "C" void kernel_launch(void* const* d_in, const int* in_sizes, int n_in,
                              void* d_out, int out_size)
{
    (void)in_sizes; (void)n_in; (void)out_size;
    const float* f0       = (const float*)d_in[0];
    const float* f1       = (const float*)d_in[1];
    const float* rbf      = (const float*)d_in[2];
    const float* gt_edge  = (const float*)d_in[3];
    const float* W1       = (const float*)d_in[4];
    const float* b1       = (const float*)d_in[5];
    const float* W2       = (const float*)d_in[6];
    const float* b2       = (const float*)d_in[7];
    const float* W3       = (const float*)d_in[8];
    const float* b3       = (const float*)d_in[9];
    const float* ln_g0    = (const float*)d_in[10];
    const float* ln_b0    = (const float*)d_in[11];
    const float* ln_g1    = (const float*)d_in[12];
    const float* ln_b1    = (const float*)d_in[13];
    const float* gate_W0  = (const float*)d_in[14];
    const float* gate_b0  = (const float*)d_in[15];
    const float* gate_W1  = (const float*)d_in[16];
    const float* gate_b1  = (const float*)d_in[17];
    const float* res_W0   = (const float*)d_in[18];
    const float* res_W1   = (const float*)d_in[19];
    const int* nbr        = (const int*)d_in[20];
    float* out = (float*)d_out;

    tw3_kernel<<<320, 256>>>(W3, b3);
    mlp_kernel<<<dim3(NROW / 128, 5, 1), 256>>>(rbf, W1, b1, W2, b2);
    gtt2_kernel<<<NN, 256, SM2_BYTES>>>(f0, f1, gt_edge,
                                        ln_g0, ln_b0, ln_g1, ln_b1,
                                        gate_W0, gate_b0, gate_W1, gate_b1,
                                        res_W0, res_W1, nbr, out);
}

// round 17
// speedup vs baseline: 1.1898x; 1.0043x over previous
#include <cuda_runtime.h>

#define NN   8192
#define KK   32
#define NROW (NN * KK)     // 262144 edge rows
#define HH   64

typedef unsigned long long ull;

// Scratch: h2 activations (320 MB) + transposed W3/b3. All fully rewritten
// before being read on every call (deterministic).
__device__ float g_h2[5L * NROW * HH];
__device__ float g_W3T[5 * 64 * 4 * 16 * 4];   // [t][h][c4][o][cc]
__device__ float g_b3T[5 * 4 * 16 * 4];        // [t][c4][o][cc]

__device__ __forceinline__ float siluf(float x) {
    return __fdividef(x, 1.0f + __expf(-x));
}
__device__ __forceinline__ float sigmf(float x) {
    return __fdividef(1.0f, 1.0f + __expf(-x));
}

// ---- packed f32x2 (FFMA2) helpers ----
__device__ __forceinline__ ull pk2(float x, float y) {
    ull r; asm("mov.b64 %0,{%1,%2};" : "=l"(r) : "f"(x), "f"(y)); return r;
}
__device__ __forceinline__ void upk2(float& x, float& y, ull v) {
    asm("mov.b64 {%0,%1},%2;" : "=f"(x), "=f"(y) : "l"(v));
}
__device__ __forceinline__ ull fma2(ull a, ull b, ull c) {
    ull d; asm("fma.rn.f32x2 %0,%1,%2,%3;" : "=l"(d) : "l"(a), "l"(b), "l"(c));
    return d;
}

// =========================================================================
// Kernel 0: transpose W3 -> W3T[t][h][c4][o][cc], b3 -> b3T[t][c4][o][cc].
// =========================================================================
__global__ __launch_bounds__(256)
void tw3_kernel(const float* __restrict__ W3, const float* __restrict__ b3)
{
    int g = blockIdx.x * 256 + threadIdx.x;
    if (g < 81920) {
        int cc = g & 3, o = (g >> 2) & 15, c4 = (g >> 6) & 3;
        int h = (g >> 8) & 63, t = g >> 14;
        g_W3T[g] = W3[t * 16384 + h * 256 + (c4 * 4 + cc) * 16 + o];
    }
    if (g < 1280) {
        int cc = g & 3, o = (g >> 2) & 15, c4 = (g >> 6) & 3, t = g >> 8;
        g_b3T[g] = b3[t * 256 + (c4 * 4 + cc) * 16 + o];
    }
}

// =========================================================================
// Kernel 1: radial MLP (rbf -> silu -> silu -> h2), batched GEMM (proven).
// =========================================================================
__global__ __launch_bounds__(256)
void mlp_kernel(const float* __restrict__ rbf,
                const float* __restrict__ W1, const float* __restrict__ b1,
                const float* __restrict__ W2, const float* __restrict__ b2)
{
    __shared__ float rbfT[16 * 132];
    __shared__ float h1T[64 * 132];

    const int t    = blockIdx.y;
    const int base = blockIdx.x * 128;
    const int tid  = threadIdx.x;
    const float* W1t = W1 + t * 1024;
    const float* W2t = W2 + t * 4096;

    #pragma unroll
    for (int it = 0; it < 2; it++) {
        int idx = it * 256 + tid;
        int row = idx >> 2, cb = (idx & 3) * 4;
        float4 v = *(const float4*)&rbf[(base + row) * 16 + cb];
        rbfT[(cb + 0) * 132 + row] = v.x;
        rbfT[(cb + 1) * 132 + row] = v.y;
        rbfT[(cb + 2) * 132 + row] = v.z;
        rbfT[(cb + 3) * 132 + row] = v.w;
    }
    __syncthreads();

    const int hg = tid & 15, rg = tid >> 4;
    const int h0 = hg * 4,  r0 = rg * 8;

    ull acc[8][2];

    {   // h1 = silu(rbf @ W1 + b1)
        ulonglong2 bp = *(const ulonglong2*)&b1[t * 64 + h0];
        #pragma unroll
        for (int k = 0; k < 8; k++) { acc[k][0] = bp.x; acc[k][1] = bp.y; }
        #pragma unroll
        for (int r = 0; r < 16; r++) {
            ulonglong2 wv = *(const ulonglong2*)&W1t[r * 64 + h0];
            float4 a0 = *(const float4*)&rbfT[r * 132 + r0];
            float4 a1 = *(const float4*)&rbfT[r * 132 + r0 + 4];
            ull ap[8];
            ap[0] = pk2(a0.x, a0.x); ap[1] = pk2(a0.y, a0.y);
            ap[2] = pk2(a0.z, a0.z); ap[3] = pk2(a0.w, a0.w);
            ap[4] = pk2(a1.x, a1.x); ap[5] = pk2(a1.y, a1.y);
            ap[6] = pk2(a1.z, a1.z); ap[7] = pk2(a1.w, a1.w);
            #pragma unroll
            for (int k = 0; k < 8; k++) {
                acc[k][0] = fma2(ap[k], wv.x, acc[k][0]);
                acc[k][1] = fma2(ap[k], wv.y, acc[k][1]);
            }
        }
        float sv[8][4];
        #pragma unroll
        for (int k = 0; k < 8; k++) {
            float x0, x1, x2, x3;
            upk2(x0, x1, acc[k][0]);
            upk2(x2, x3, acc[k][1]);
            sv[k][0] = siluf(x0); sv[k][1] = siluf(x1);
            sv[k][2] = siluf(x2); sv[k][3] = siluf(x3);
        }
        #pragma unroll
        for (int c = 0; c < 4; c++) {
            *(float4*)&h1T[(h0 + c) * 132 + r0] =
                make_float4(sv[0][c], sv[1][c], sv[2][c], sv[3][c]);
            *(float4*)&h1T[(h0 + c) * 132 + r0 + 4] =
                make_float4(sv[4][c], sv[5][c], sv[6][c], sv[7][c]);
        }
    }
    __syncthreads();

    {   // h2 = silu(h1 @ W2 + b2)
        ulonglong2 bp = *(const ulonglong2*)&b2[t * 64 + h0];
        #pragma unroll
        for (int k = 0; k < 8; k++) { acc[k][0] = bp.x; acc[k][1] = bp.y; }
        #pragma unroll 16
        for (int r = 0; r < 64; r++) {
            ulonglong2 wv = *(const ulonglong2*)&W2t[r * 64 + h0];
            float4 a0 = *(const float4*)&h1T[r * 132 + r0];
            float4 a1 = *(const float4*)&h1T[r * 132 + r0 + 4];
            ull ap[8];
            ap[0] = pk2(a0.x, a0.x); ap[1] = pk2(a0.y, a0.y);
            ap[2] = pk2(a0.z, a0.z); ap[3] = pk2(a0.w, a0.w);
            ap[4] = pk2(a1.x, a1.x); ap[5] = pk2(a1.y, a1.y);
            ap[6] = pk2(a1.z, a1.z); ap[7] = pk2(a1.w, a1.w);
            #pragma unroll
            for (int k = 0; k < 8; k++) {
                acc[k][0] = fma2(ap[k], wv.x, acc[k][0]);
                acc[k][1] = fma2(ap[k], wv.y, acc[k][1]);
            }
        }
        float* dst = g_h2 + (long)(t * NROW + base) * 64;
        #pragma unroll
        for (int k = 0; k < 8; k++) {
            float x0, x1, x2, x3;
            upk2(x0, x1, acc[k][0]);
            upk2(x2, x3, acc[k][1]);
            *(float4*)&dst[(r0 + k) * 64 + h0] =
                make_float4(siluf(x0), siluf(x1), siluf(x2), siluf(x3));
        }
    }
}

// =========================================================================
// Kernel 2: 4 NODES PER BLOCK. Contraction + W3 + norm/gates/residual.
// W3/b3 weights register-resident once per path, reused across 4 nodes.
// =========================================================================
#define NPB 4
#define OFF_E    0        // 4*128  = 512
#define OFF_F0N  512      // 4*512  = 2048
#define OFF_F1N  2560     // 4*1536 = 6144
#define OFF_CTR  8704     // 4*1536 = 6144
#define OFF_M    14848    // 4*3120 = 12480  (nb_s aliases first 128 ints early)
#define OFF_RED  27328    // 768 (reused per node; also post-norm scratch 4*192)
#define OFF_ACC0 28096    // 4*16
#define OFF_ACC1 28160    // 4*48
#define SM2_FLOATS 28352
#define SM2_BYTES (SM2_FLOATS * 4)   // 113,408 B -> 2 blocks/SM

__global__ __launch_bounds__(256, 2)
void gtt2_kernel(const float* __restrict__ f0, const float* __restrict__ f1,
                 const float* __restrict__ gt_edge,
                 const float* __restrict__ ln_g0, const float* __restrict__ ln_b0,
                 const float* __restrict__ ln_g1, const float* __restrict__ ln_b1,
                 const float* __restrict__ gate_W0, const float* __restrict__ gate_b0,
                 const float* __restrict__ gate_W1, const float* __restrict__ gate_b1,
                 const float* __restrict__ res_W0, const float* __restrict__ res_W1,
                 const int* __restrict__ nbr_idx,
                 float* __restrict__ out)
{
    extern __shared__ float sm[];
    float* e_s   = sm + OFF_E;
    float* f0n_s = sm + OFF_F0N;
    float* f1n_s = sm + OFF_F1N;
    float* ctr_s = sm + OFF_CTR;
    float* M_s   = sm + OFF_M;
    float* red_s = sm + OFF_RED;
    float* acc0  = sm + OFF_ACC0;   // [n][16]
    float* acc1  = sm + OFF_ACC1;   // [n][48]
    int*   nb_s  = (int*)(sm + OFF_M);   // 128 ints; dead before M_s written

    const int tid = threadIdx.x;
    const int bi  = blockIdx.x;          // 4 nodes: bi*4 .. bi*4+3

    // ---- loads ----
    if (tid < 128) nb_s[tid] = nbr_idx[bi * 128 + tid];
    for (int idx = tid; idx < 512; idx += 256)
        e_s[idx] = gt_edge[bi * 512 + idx];
    sm[OFF_ACC0 + tid] = 0.f;            // zero acc0+acc1 (256 floats)
    __syncthreads();

    for (int idx = tid; idx < 2048; idx += 256) {
        int n = idx >> 9, j = (idx >> 4) & 31, c = idx & 15;
        f0n_s[idx] = f0[nb_s[n * 32 + j] * 16 + c];
    }
    for (int idx = tid; idx < 6144; idx += 256) {
        int n = idx / 1536, rem = idx - n * 1536;
        int j = rem / 48, r = rem - j * 48;
        f1n_s[idx] = f1[nb_s[n * 32 + j] * 48 + r];
    }
    __syncthreads();

    #pragma unroll
    for (int t = 0; t < 5; t++) {
        const int dd = (t == 0 || t == 3) ? 1 : 3;
        const int ot = (t == 0 || t == 3) ? 0 : 1;
        const int md = 16 * dd;
        const float* h2b = g_h2 + (long)(t * NROW + bi * 128) * 64;

        // ---- ctr for all 4 nodes ----
        for (int idx = tid; idx < 4 * 32 * md; idx += 256) {
            int n, rem;
            if (md == 16) { n = idx >> 9; rem = idx & 511; }
            else          { n = idx / 1536; rem = idx - n * 1536; }
            int j = rem / md, cd = rem - j * md;
            const float* e_n   = e_s   + n * 128 + j * 4;
            const float* f0n_n = f0n_s + n * 512 + j * 16;
            const float* f1n_n = f1n_s + n * 1536 + j * 48;
            float v;
            if (t == 0) {
                v = e_n[0] * f0n_n[cd];
            } else if (t == 1) {
                int c = cd / 3, d = cd - c * 3;
                v = e_n[1 + d] * f0n_n[c];
            } else if (t == 2) {
                int c = cd / 3, d = cd - c * 3;
                v = e_n[0] * f1n_n[c * 3 + d];
            } else if (t == 3) {
                v = e_n[1] * f1n_n[cd * 3]
                  + e_n[2] * f1n_n[cd * 3 + 1]
                  + e_n[3] * f1n_n[cd * 3 + 2];
            } else {
                int c = cd / 3, d = cd - c * 3;
                int d1 = (d + 1) % 3, d2 = (d + 2) % 3;
                v = f1n_n[c * 3 + d1] * e_n[1 + d2]
                  - f1n_n[c * 3 + d2] * e_n[1 + d1];
            }
            ctr_s[n * 1536 + j * 48 + cd] = v;
        }
        __syncthreads();

        // ---- M_n[h][cd] = sum_j h2[j][h]*ctr[j][cd], 64 threads/node ----
        {
            const int n  = tid >> 6, l = tid & 63;
            const int hq = l & 15, cq = l >> 4;           // h-quad, col-group
            const int nq = (dd == 3) ? 3 : 1;             // float4 quads per cq
            const int cb = cq * nq * 4;                   // col base
            const float* h2n = h2b + n * 2048;
            const float* cn  = ctr_s + n * 1536;
            float4 a[4][3];
            #pragma unroll
            for (int x = 0; x < 4; x++)
                #pragma unroll
                for (int q = 0; q < 3; q++)
                    a[x][q] = make_float4(0.f, 0.f, 0.f, 0.f);
            #pragma unroll 4
            for (int j = 0; j < 32; j++) {
                float4 hv = *(const float4*)&h2n[j * 64 + hq * 4];
                #pragma unroll
                for (int q = 0; q < nq; q++) {
                    float4 cv = *(const float4*)&cn[j * 48 + cb + q * 4];
                    a[0][q].x = fmaf(hv.x, cv.x, a[0][q].x);
                    a[0][q].y = fmaf(hv.x, cv.y, a[0][q].y);
                    a[0][q].z = fmaf(hv.x, cv.z, a[0][q].z);
                    a[0][q].w = fmaf(hv.x, cv.w, a[0][q].w);
                    a[1][q].x = fmaf(hv.y, cv.x, a[1][q].x);
                    a[1][q].y = fmaf(hv.y, cv.y, a[1][q].y);
                    a[1][q].z = fmaf(hv.y, cv.z, a[1][q].z);
                    a[1][q].w = fmaf(hv.y, cv.w, a[1][q].w);
                    a[2][q].x = fmaf(hv.z, cv.x, a[2][q].x);
                    a[2][q].y = fmaf(hv.z, cv.y, a[2][q].y);
                    a[2][q].z = fmaf(hv.z, cv.z, a[2][q].z);
                    a[2][q].w = fmaf(hv.z, cv.w, a[2][q].w);
                    a[3][q].x = fmaf(hv.w, cv.x, a[3][q].x);
                    a[3][q].y = fmaf(hv.w, cv.y, a[3][q].y);
                    a[3][q].z = fmaf(hv.w, cv.z, a[3][q].z);
                    a[3][q].w = fmaf(hv.w, cv.w, a[3][q].w);
                }
            }
            float* Mn = M_s + n * 3120;
            #pragma unroll
            for (int x = 0; x < 4; x++)
                #pragma unroll
                for (int q = 0; q < 3; q++)
                    if (q < nq)
                        *(float4*)&Mn[(hq * 4 + x) * 48 + cb + q * 4] = a[x][q];
        }
        {   // bias rows: M_n[64][cd] = sum_j ctr
            int n = tid >> 6, cd = tid & 63;
            if (cd < md) {
                const float* cn = ctr_s + n * 1536;
                float s = 0.f;
                #pragma unroll 8
                for (int j = 0; j < 32; j++) s += cn[j * 48 + cd];
                M_s[n * 3120 + 3072 + cd] = s;
            }
        }
        __syncthreads();

        // ---- msg = M x W3: weights in regs once, loop 4 nodes ----
        {
            const int o = tid & 15, grp = tid >> 4;    // 16 grp x 16 o
            float4 wq[16];                              // [hh][c4]
            #pragma unroll
            for (int hh = 0; hh < 4; hh++)
                #pragma unroll
                for (int c4 = 0; c4 < 4; c4++)
                    wq[hh * 4 + c4] = *(const float4*)
                        &g_W3T[((t * 64 + grp * 4 + hh) * 4 + c4) * 64 + o * 4];

            #define GTT_W(ARR, base, c_) ((c_ & 3) == 0 ? ARR[(base)+(c_>>2)].x : \
                                          (c_ & 3) == 1 ? ARR[(base)+(c_>>2)].y : \
                                          (c_ & 3) == 2 ? ARR[(base)+(c_>>2)].z : \
                                                          ARR[(base)+(c_>>2)].w)
            #define GTT_ACC(vv, idx, ARR, base) do {                      \
                const int c_ = (idx) / 3, d_ = (idx) % 3;                 \
                const float w_ = GTT_W(ARR, base, c_);                    \
                if (d_ == 0)      p0 = fmaf((vv), w_, p0);                \
                else if (d_ == 1) p1 = fmaf((vv), w_, p1);                \
                else              p2 = fmaf((vv), w_, p2);                \
            } while (0)

            #pragma unroll
            for (int n = 0; n < 4; n++) {
                const float* Mn = M_s + n * 3120;
                float p0 = 0.f, p1 = 0.f, p2 = 0.f;
                #pragma unroll
                for (int hh = 0; hh < 4; hh++) {
                    const float4* m4 = (const float4*)(Mn + (grp * 4 + hh) * 48);
                    if (dd == 1) {
                        #pragma unroll
                        for (int q = 0; q < 4; q++) {
                            float4 m = m4[q];
                            p0 = fmaf(m.x, wq[hh * 4 + q].x, p0);
                            p0 = fmaf(m.y, wq[hh * 4 + q].y, p0);
                            p0 = fmaf(m.z, wq[hh * 4 + q].z, p0);
                            p0 = fmaf(m.w, wq[hh * 4 + q].w, p0);
                        }
                    } else {
                        #pragma unroll
                        for (int q = 0; q < 12; q++) {
                            float4 m = m4[q];
                            GTT_ACC(m.x, 4 * q + 0, wq, hh * 4);
                            GTT_ACC(m.y, 4 * q + 1, wq, hh * 4);
                            GTT_ACC(m.z, 4 * q + 2, wq, hh * 4);
                            GTT_ACC(m.w, 4 * q + 3, wq, hh * 4);
                        }
                    }
                }
                if (grp == 0) {   // bias row with b3T weights
                    float4 bq[4];
                    #pragma unroll
                    for (int c4 = 0; c4 < 4; c4++)
                        bq[c4] = *(const float4*)&g_b3T[(t * 4 + c4) * 64 + o * 4];
                    const float4* m4 = (const float4*)(Mn + 3072);
                    if (dd == 1) {
                        #pragma unroll
                        for (int q = 0; q < 4; q++) {
                            float4 m = m4[q];
                            p0 = fmaf(m.x, bq[q].x, p0);
                            p0 = fmaf(m.y, bq[q].y, p0);
                            p0 = fmaf(m.z, bq[q].z, p0);
                            p0 = fmaf(m.w, bq[q].w, p0);
                        }
                    } else {
                        #pragma unroll
                        for (int q = 0; q < 12; q++) {
                            float4 m = m4[q];
                            GTT_ACC(m.x, 4 * q + 0, bq, 0);
                            GTT_ACC(m.y, 4 * q + 1, bq, 0);
                            GTT_ACC(m.z, 4 * q + 2, bq, 0);
                            GTT_ACC(m.w, 4 * q + 3, bq, 0);
                        }
                    }
                }
                red_s[grp * 48 + o * dd + 0] = p0;
                if (dd == 3) {
                    red_s[grp * 48 + o * dd + 1] = p1;
                    red_s[grp * 48 + o * dd + 2] = p2;
                }
                __syncthreads();
                if (tid < md) {
                    float s = 0.f;
                    #pragma unroll
                    for (int g = 0; g < 16; g++) s += red_s[g * 48 + tid];
                    if (ot == 0) acc0[n * 16 + tid] += s;
                    else         acc1[n * 48 + tid] += s;
                }
                __syncthreads();
            }
            #undef GTT_ACC
            #undef GTT_W
        }
    }

    // ---- type_norm, gates, residual: 64 threads per node ----
    {
        const int n = tid >> 6, ln = tid & 63;
        const int i = bi * 4 + n;
        float* nrm = red_s + n * 192;        // 32
        float* f0g = nrm + 32;               // 16
        float* o1n = nrm + 48;               // 48
        float* g1s = nrm + 96;               // 16
        const float* a0 = acc0 + n * 16;
        const float* a1 = acc1 + n * 48;

        if (ln < 16) {
            nrm[ln] = fmaxf(fabsf(a0[ln]), 1e-8f);
            float a = a1[ln * 3], b = a1[ln * 3 + 1], c = a1[ln * 3 + 2];
            nrm[16 + ln] = fmaxf(sqrtf(a * a + b * b + c * c), 1e-8f);
        }
        __syncthreads();
        if (ln < 16) {
            float mu0 = 0.f, mu1 = 0.f;
            #pragma unroll
            for (int c = 0; c < 16; c++) { mu0 += nrm[c]; mu1 += nrm[16 + c]; }
            mu0 *= 0.0625f; mu1 *= 0.0625f;
            float v0 = 0.f, v1 = 0.f;
            #pragma unroll
            for (int c = 0; c < 16; c++) {
                float d0 = nrm[c] - mu0;      v0 += d0 * d0;
                float d1 = nrm[16 + c] - mu1; v1 += d1 * d1;
            }
            v0 *= 0.0625f; v1 *= 0.0625f;
            float sc0 = (nrm[ln] - mu0) * rsqrtf(v0 + 1e-5f) * ln_g0[ln] + ln_b0[ln];
            float sc1 = (nrm[16 + ln] - mu1) * rsqrtf(v1 + 1e-5f) * ln_g1[ln] + ln_b1[ln];
            f0g[ln] = a0[ln] / nrm[ln] * sc0;
            float inv1 = sc1 / nrm[16 + ln];
            o1n[ln * 3 + 0] = a1[ln * 3 + 0] * inv1;
            o1n[ln * 3 + 1] = a1[ln * 3 + 1] * inv1;
            o1n[ln * 3 + 2] = a1[ln * 3 + 2] * inv1;
        }
        __syncthreads();
        if (ln < 16) {
            float z0 = gate_b0[ln], z1 = gate_b1[ln];
            #pragma unroll
            for (int c = 0; c < 16; c++) {
                z0 = fmaf(f0g[c], gate_W0[c * 16 + ln], z0);
                z1 = fmaf(f0g[c], gate_W1[c * 16 + ln], z1);
            }
            float g0 = sigmf(z0);
            g1s[ln] = sigmf(z1);
            float r = 0.f;
            #pragma unroll
            for (int c = 0; c < 16; c++)
                r = fmaf(f0[i * 16 + c], res_W0[c * 16 + ln], r);
            out[i * 16 + ln] = f0g[ln] * g0 + r;
        }
        __syncthreads();
        if (ln < 48) {
            int o = ln / 3, d = ln - o * 3;
            float r = 0.f;
            #pragma unroll
            for (int c = 0; c < 16; c++)
                r = fmaf(f1[(i * 16 + c) * 3 + d], res_W1[c * 16 + o], r);
            out[NN * 16 + i * 48 + ln] = o1n[ln] * g1s[o] + r;
        }
    }
}

extern "C" void kernel_launch(void* const* d_in, const int* in_sizes, int n_in,
                              void* d_out, int out_size)
{
    (void)in_sizes; (void)n_in; (void)out_size;
    const float* f0       = (const float*)d_in[0];
    const float* f1       = (const float*)d_in[1];
    const float* rbf      = (const float*)d_in[2];
    const float* gt_edge  = (const float*)d_in[3];
    const float* W1       = (const float*)d_in[4];
    const float* b1       = (const float*)d_in[5];
    const float* W2       = (const float*)d_in[6];
    const float* b2       = (const float*)d_in[7];
    const float* W3       = (const float*)d_in[8];
    const float* b3       = (const float*)d_in[9];
    const float* ln_g0    = (const float*)d_in[10];
    const float* ln_b0    = (const float*)d_in[11];
    const float* ln_g1    = (const float*)d_in[12];
    const float* ln_b1    = (const float*)d_in[13];
    const float* gate_W0  = (const float*)d_in[14];
    const float* gate_b0  = (const float*)d_in[15];
    const float* gate_W1  = (const float*)d_in[16];
    const float* gate_b1  = (const float*)d_in[17];
    const float* res_W0   = (const float*)d_in[18];
    const float* res_W1   = (const float*)d_in[19];
    const int* nbr        = (const int*)d_in[20];
    float* out = (float*)d_out;

    static int smem_set = 0;
    if (!smem_set) {
        cudaFuncSetAttribute(gtt2_kernel,
                             cudaFuncAttributeMaxDynamicSharedMemorySize,
                             SM2_BYTES);
        smem_set = 1;
    }

    tw3_kernel<<<320, 256>>>(W3, b3);
    mlp_kernel<<<dim3(NROW / 128, 5, 1), 256>>>(rbf, W1, b1, W2, b2);
    gtt2_kernel<<<NN / NPB, 256, SM2_BYTES>>>(f0, f1, gt_edge,
                                              ln_g0, ln_b0, ln_g1, ln_b1,
                                              gate_W0, gate_b0, gate_W1, gate_b1,
                                              res_W0, res_W1, nbr, out);
}